// round 1
// baseline (speedup 1.0000x reference)
#include <cuda_runtime.h>
#include <cuda_bf16.h>
#include <cstdint>

// Problem constants
#define BATCH 4
#define TSEQ  2048
#define DMODEL 1024
#define DK 128
#define SM_SCALE 0.08838834764831845f  // 1/sqrt(128)

// -------------------- scratch (device globals, allocation-free) --------------------
__device__ float g_Q[BATCH * TSEQ * DK];
__device__ float g_K[BATCH * TSEQ * DK];
__device__ float g_V[BATCH * TSEQ * DK];
__device__ float g_O[BATCH * TSEQ * DK];

// -------------------- generic 64x64x16 fp32 GEMM body --------------------
// C[M,N] = A[M,K] @ B[K,N], all row-major. grid.y tiles M, grid.x tiles N.
// 256 threads, each computes 4x4.
__device__ __forceinline__ void gemm_body(const float* __restrict__ A,
                                          const float* __restrict__ B,
                                          float* __restrict__ C,
                                          int N, int K)
{
    __shared__ float As[16][68];   // k-major, padded (68%4==0 -> v4-able, conflict-free broadcast)
    __shared__ float Bs[16][64];

    const int t  = threadIdx.x;
    const int tx = t & 15;
    const int ty = t >> 4;
    const int m0 = blockIdx.y * 64;
    const int n0 = blockIdx.x * 64;

    float acc[4][4];
#pragma unroll
    for (int i = 0; i < 4; i++)
#pragma unroll
        for (int j = 0; j < 4; j++) acc[i][j] = 0.f;

    for (int k0 = 0; k0 < K; k0 += 16) {
        // load A tile 64x16 (transposed store)
#pragma unroll
        for (int i = 0; i < 4; i++) {
            int idx = t + i * 256;
            int r = idx >> 4, c = idx & 15;
            As[c][r] = A[(size_t)(m0 + r) * K + k0 + c];
        }
        // load B tile 16x64 (natural)
#pragma unroll
        for (int i = 0; i < 4; i++) {
            int idx = t + i * 256;
            int r = idx >> 6, c = idx & 63;
            Bs[r][c] = B[(size_t)(k0 + r) * N + n0 + c];
        }
        __syncthreads();
#pragma unroll
        for (int kk = 0; kk < 16; kk++) {
            float a[4], bb[4];
#pragma unroll
            for (int i = 0; i < 4; i++) a[i] = As[kk][ty * 4 + i];
#pragma unroll
            for (int j = 0; j < 4; j++) bb[j] = Bs[kk][tx * 4 + j];
#pragma unroll
            for (int i = 0; i < 4; i++)
#pragma unroll
                for (int j = 0; j < 4; j++) acc[i][j] = fmaf(a[i], bb[j], acc[i][j]);
        }
        __syncthreads();
    }

#pragma unroll
    for (int i = 0; i < 4; i++) {
        float4 v = make_float4(acc[i][0], acc[i][1], acc[i][2], acc[i][3]);
        *(float4*)(C + (size_t)(m0 + ty * 4 + i) * N + n0 + tx * 4) = v;
    }
}

// QKV: grid (2, 128, 3). z selects weight/output.
__global__ __launch_bounds__(256) void qkv_kernel(const float* __restrict__ x,
                                                  const float* __restrict__ Wq,
                                                  const float* __restrict__ Wk,
                                                  const float* __restrict__ Wv)
{
    const float* W;
    float* O;
    if (blockIdx.z == 0)      { W = Wq; O = g_Q; }
    else if (blockIdx.z == 1) { W = Wk; O = g_K; }
    else                      { W = Wv; O = g_V; }
    gemm_body(x, W, O, DK, DMODEL);
}

// Output projection: grid (16, 128).
__global__ __launch_bounds__(256) void oproj_kernel(const float* __restrict__ Wo,
                                                    float* __restrict__ out)
{
    gemm_body(g_O, Wo, out, DMODEL, DK);
}

// -------------------- flash attention --------------------
// 32-query x 64-key tiles, dk=128. 128 threads (tx 0..15, ty 0..7).
// smem layout (floats):
#define QS_OFF 0                         // Qs[128][33]  k-major
#define KS_OFF (QS_OFF + 128 * 33)       // Ks[128][65]  k-major
#define VS_OFF (KS_OFF + 128 * 65)       // Vs[64][128]  natural
#define PS_OFF (VS_OFF + 64 * 128)       // Ps[64][33]   col-major (key-major)
#define M_OFF  (PS_OFF + 64 * 33)
#define L_OFF  (M_OFF + 32)
#define F_OFF  (L_OFF + 32)
#define ATTN_SMEM_FLOATS (F_OFF + 32)
#define ATTN_SMEM_BYTES  (ATTN_SMEM_FLOATS * 4)

__global__ __launch_bounds__(128, 2) void attn_kernel()
{
    extern __shared__ float sm[];
    float* Qs = sm + QS_OFF;
    float* Ks = sm + KS_OFF;
    float* Vs = sm + VS_OFF;
    float* Ps = sm + PS_OFF;

    const int t  = threadIdx.x;
    const int tx = t & 15;
    const int ty = t >> 4;
    const int b  = blockIdx.y;
    const int qt = (int)gridDim.x - 1 - (int)blockIdx.x;  // heavy tiles scheduled first
    const int q0 = qt * 32;

    // load Q tile [32][128] -> Qs k-major
    const float* Qg = g_Q + ((size_t)b * TSEQ + q0) * DK;
#pragma unroll
    for (int i = 0; i < 8; i++) {
        int idx4 = t + i * 128;
        int r = idx4 >> 5, c4 = idx4 & 31;
        float4 v = *(const float4*)(Qg + r * DK + c4 * 4);
        Qs[(c4 * 4 + 0) * 33 + r] = v.x;
        Qs[(c4 * 4 + 1) * 33 + r] = v.y;
        Qs[(c4 * 4 + 2) * 33 + r] = v.z;
        Qs[(c4 * 4 + 3) * 33 + r] = v.w;
    }
    if (t < 32) { sm[M_OFF + t] = -3.0e38f; sm[L_OFF + t] = 0.f; }

    float o[4][8];
#pragma unroll
    for (int i = 0; i < 4; i++)
#pragma unroll
        for (int j = 0; j < 8; j++) o[i][j] = 0.f;

    const int nK = (q0 + 32 + 63) >> 6;   // causal: key chunks covering keys <= q0+31

    for (int kt = 0; kt < nK; kt++) {
        const int k0 = kt * 64;
        __syncthreads();   // prev iter consumers done before overwriting tiles

        // load K chunk [64][128] -> Ks k-major
        const float* Kg = g_K + ((size_t)b * TSEQ + k0) * DK;
#pragma unroll
        for (int i = 0; i < 16; i++) {
            int idx4 = t + i * 128;
            int r = idx4 >> 5, c4 = idx4 & 31;
            float4 v = *(const float4*)(Kg + r * DK + c4 * 4);
            Ks[(c4 * 4 + 0) * 65 + r] = v.x;
            Ks[(c4 * 4 + 1) * 65 + r] = v.y;
            Ks[(c4 * 4 + 2) * 65 + r] = v.z;
            Ks[(c4 * 4 + 3) * 65 + r] = v.w;
        }
        // load V chunk natural
        const float* Vg = g_V + ((size_t)b * TSEQ + k0) * DK;
#pragma unroll
        for (int i = 0; i < 16; i++) {
            int idx4 = t + i * 128;
            int r = idx4 >> 5, c4 = idx4 & 31;
            *(float4*)(Vs + r * DK + c4 * 4) = *(const float4*)(Vg + r * DK + c4 * 4);
        }
        __syncthreads();

        // S = Q @ K^T : each thread 4 rows (ty*4) x 4 cols (tx*4)
        float s[4][4];
#pragma unroll
        for (int i = 0; i < 4; i++)
#pragma unroll
            for (int j = 0; j < 4; j++) s[i][j] = 0.f;

#pragma unroll 4
        for (int kk = 0; kk < 128; kk++) {
            float a[4], bb[4];
#pragma unroll
            for (int i = 0; i < 4; i++) a[i] = Qs[kk * 33 + ty * 4 + i];
#pragma unroll
            for (int j = 0; j < 4; j++) bb[j] = Ks[kk * 65 + tx * 4 + j];
#pragma unroll
            for (int i = 0; i < 4; i++)
#pragma unroll
                for (int j = 0; j < 4; j++) s[i][j] = fmaf(a[i], bb[j], s[i][j]);
        }

        // scale + causal mask, store transposed (key-major) into Ps
#pragma unroll
        for (int i = 0; i < 4; i++) {
            int qrow = q0 + ty * 4 + i;
#pragma unroll
            for (int j = 0; j < 4; j++) {
                int kcol = k0 + tx * 4 + j;
                float v = s[i][j] * SM_SCALE;
                Ps[(tx * 4 + j) * 33 + (ty * 4 + i)] = (kcol > qrow) ? -1.0e30f : v;
            }
        }
        __syncthreads();

        // online softmax: one thread per query row
        if (t < 32) {
            const int r = t;
            float mold = sm[M_OFF + r];
            float mx = mold;
#pragma unroll 8
            for (int c = 0; c < 64; c++) mx = fmaxf(mx, Ps[c * 33 + r]);
            float ssum = 0.f;
#pragma unroll 8
            for (int c = 0; c < 64; c++) {
                float p = __expf(Ps[c * 33 + r] - mx);
                Ps[c * 33 + r] = p;
                ssum += p;
            }
            float f = __expf(mold - mx);
            sm[L_OFF + r] = sm[L_OFF + r] * f + ssum;
            sm[M_OFF + r] = mx;
            sm[F_OFF + r] = f;
        }
        __syncthreads();

        // rescale accumulators, then O += P @ V : 4 rows x 8 cols (tx*8)
#pragma unroll
        for (int i = 0; i < 4; i++) {
            float f = sm[F_OFF + ty * 4 + i];
#pragma unroll
            for (int j = 0; j < 8; j++) o[i][j] *= f;
        }
#pragma unroll 2
        for (int kk = 0; kk < 64; kk++) {
            float a[4], bb[8];
#pragma unroll
            for (int i = 0; i < 4; i++) a[i] = Ps[kk * 33 + ty * 4 + i];
#pragma unroll
            for (int j = 0; j < 8; j++) bb[j] = Vs[kk * 128 + tx * 8 + j];
#pragma unroll
            for (int i = 0; i < 4; i++)
#pragma unroll
                for (int j = 0; j < 8; j++) o[i][j] = fmaf(a[i], bb[j], o[i][j]);
        }
    }

    // epilogue: normalize by l, store to g_O
#pragma unroll
    for (int i = 0; i < 4; i++) {
        float inv = 1.0f / sm[L_OFF + ty * 4 + i];
        float* dst = g_O + ((size_t)b * TSEQ + q0 + ty * 4 + i) * DK + tx * 8;
        float4 v0 = make_float4(o[i][0] * inv, o[i][1] * inv, o[i][2] * inv, o[i][3] * inv);
        float4 v1 = make_float4(o[i][4] * inv, o[i][5] * inv, o[i][6] * inv, o[i][7] * inv);
        *(float4*)(dst + 0) = v0;
        *(float4*)(dst + 4) = v1;
    }
}

// -------------------- launch --------------------
extern "C" void kernel_launch(void* const* d_in, const int* in_sizes, int n_in,
                              void* d_out, int out_size)
{
    const float* x  = (const float*)d_in[0];
    const float* Wq = (const float*)d_in[1];
    const float* Wk = (const float*)d_in[2];
    const float* Wv = (const float*)d_in[3];
    const float* Wo = (const float*)d_in[4];
    float* out = (float*)d_out;

    static bool attr_set = false;
    if (!attr_set) {
        cudaFuncSetAttribute(attn_kernel, cudaFuncAttributeMaxDynamicSharedMemorySize,
                             ATTN_SMEM_BYTES);
        attr_set = true;
    }

    // 1) Q,K,V = x @ {Wq,Wk,Wv}
    {
        dim3 grid(DK / 64, (BATCH * TSEQ) / 64, 3);
        qkv_kernel<<<grid, 256>>>(x, Wq, Wk, Wv);
    }
    // 2) causal flash attention
    {
        dim3 grid(TSEQ / 32, BATCH);
        attn_kernel<<<grid, 128, ATTN_SMEM_BYTES>>>();
    }
    // 3) out = O @ Wo
    {
        dim3 grid(DMODEL / 64, (BATCH * TSEQ) / 64);
        oproj_kernel<<<grid, 256>>>(Wo, out);
    }
}

// round 15
// speedup vs baseline: 2.2787x; 2.2787x over previous
#include <cuda_runtime.h>
#include <cuda_bf16.h>
#include <cstdint>

// Problem constants
#define BATCH 4
#define TSEQ  2048
#define DMODEL 1024
#define DK 128
#define SM_SCALE 0.08838834764831845f            // 1/sqrt(128)
#define C_LOG2  (SM_SCALE * 1.4426950408889634f) // fold log2(e) for ex2

// -------------------- scratch (device globals, allocation-free) --------------------
__device__ float g_Q[BATCH * TSEQ * DK];   // tf32-rounded fp32
__device__ float g_K[BATCH * TSEQ * DK];
__device__ float g_V[BATCH * TSEQ * DK];

__device__ __nv_bfloat16 g_xhi[BATCH * TSEQ * DMODEL];
__device__ __nv_bfloat16 g_xlo[BATCH * TSEQ * DMODEL];
__device__ __nv_bfloat16 g_wt_hi[3][DK * DMODEL];   // Wq/Wk/Wv transposed -> [N=128][K=1024]
__device__ __nv_bfloat16 g_wt_lo[3][DK * DMODEL];
__device__ __nv_bfloat16 g_wot_hi[DMODEL * DK];     // Wo transposed -> [N=1024][K=128]
__device__ __nv_bfloat16 g_wot_lo[DMODEL * DK];
__device__ __nv_bfloat16 g_Ohi[BATCH * TSEQ * DK];  // attention output hi/lo
__device__ __nv_bfloat16 g_Olo[BATCH * TSEQ * DK];

// -------------------- small helpers --------------------
__device__ __forceinline__ uint32_t f2tf32(float x) {
    uint32_t r;
    asm("cvt.rna.tf32.f32 %0, %1;" : "=r"(r) : "f"(x));
    return r;
}
__device__ __forceinline__ float ex2f(float x) {
    float r;
    asm("ex2.approx.f32 %0, %1;" : "=f"(r) : "f"(x));
    return r;
}
__device__ __forceinline__ void mma_bf16(float* c, const uint32_t* a, const uint32_t* b) {
    asm volatile(
        "mma.sync.aligned.m16n8k16.row.col.f32.bf16.bf16.f32 "
        "{%0,%1,%2,%3}, {%4,%5,%6,%7}, {%8,%9}, {%0,%1,%2,%3};"
        : "+f"(c[0]), "+f"(c[1]), "+f"(c[2]), "+f"(c[3])
        : "r"(a[0]), "r"(a[1]), "r"(a[2]), "r"(a[3]), "r"(b[0]), "r"(b[1]));
}
__device__ __forceinline__ void mma_tf32(float* c, const uint32_t* a, const uint32_t* b) {
    asm volatile(
        "mma.sync.aligned.m16n8k8.row.col.f32.tf32.tf32.f32 "
        "{%0,%1,%2,%3}, {%4,%5,%6,%7}, {%8,%9}, {%0,%1,%2,%3};"
        : "+f"(c[0]), "+f"(c[1]), "+f"(c[2]), "+f"(c[3])
        : "r"(a[0]), "r"(a[1]), "r"(a[2]), "r"(a[3]), "r"(b[0]), "r"(b[1]));
}
__device__ __forceinline__ void bf16split2(float v0, float v1, uint32_t& hi, uint32_t& lo) {
    __nv_bfloat16 h0 = __float2bfloat16(v0), h1 = __float2bfloat16(v1);
    __nv_bfloat16 l0 = __float2bfloat16(v0 - __bfloat162float(h0));
    __nv_bfloat16 l1 = __float2bfloat16(v1 - __bfloat162float(h1));
    hi = (uint32_t)__bfloat16_as_ushort(h0) | ((uint32_t)__bfloat16_as_ushort(h1) << 16);
    lo = (uint32_t)__bfloat16_as_ushort(l0) | ((uint32_t)__bfloat16_as_ushort(l1) << 16);
}

// -------------------- convert kernels --------------------
__global__ __launch_bounds__(256) void convert_x_kernel(const float* __restrict__ x) {
    size_t i = ((size_t)blockIdx.x * 256 + threadIdx.x) * 4;
    float4 v = *(const float4*)(x + i);
    uint32_t h0, l0, h1, l1;
    bf16split2(v.x, v.y, h0, l0);
    bf16split2(v.z, v.w, h1, l1);
    *(uint2*)(g_xhi + i) = make_uint2(h0, h1);
    *(uint2*)(g_xlo + i) = make_uint2(l0, l1);
}

__global__ __launch_bounds__(256) void convert_w_kernel(const float* __restrict__ Wq,
                                                        const float* __restrict__ Wk,
                                                        const float* __restrict__ Wv,
                                                        const float* __restrict__ Wo) {
    int z = blockIdx.y;
    int o = blockIdx.x * 256 + threadIdx.x;  // 0 .. 131071
    const float* in;
    __nv_bfloat16 *oh, *ol;
    int K_, N_;
    if (z < 3) { in = (z == 0) ? Wq : (z == 1) ? Wk : Wv; oh = g_wt_hi[z]; ol = g_wt_lo[z]; K_ = DMODEL; N_ = DK; }
    else       { in = Wo; oh = g_wot_hi; ol = g_wot_lo; K_ = DK; N_ = DMODEL; }
    int k = o & (K_ - 1);
    int n = o / K_;
    float f = in[(size_t)k * N_ + n];
    __nv_bfloat16 h = __float2bfloat16(f);
    __nv_bfloat16 l = __float2bfloat16(f - __bfloat162float(h));
    oh[o] = h;
    ol[o] = l;
}

// -------------------- mma.sync bf16-split GEMM --------------------
// C[m0:+64, n0:+128] = A[m0:+64, :K] @ B[n0:+128, :K]^T, fp32 acc.
// A,B pre-split hi/lo bf16 row-major with row stride K. 256 threads, 8 warps.
// Warp (wm=wid>>1, wn=wid&1): tile m16 (rows wm*16) x n64 (cols wn*64).
#define ASTR 40   // smem row stride (bf16): 80B -> fragment lds hits 32 distinct banks

__device__ __forceinline__ void gemm_mma_body(
    const __nv_bfloat16* __restrict__ Ah, const __nv_bfloat16* __restrict__ Al,
    const __nv_bfloat16* __restrict__ Bh, const __nv_bfloat16* __restrict__ Bl,
    float* __restrict__ C, int m0, int n0, int K, int ldC, bool round_tf32)
{
    __shared__ __nv_bfloat16 sA[2][64][ASTR];
    __shared__ __nv_bfloat16 sB[2][128][ASTR];

    const int tid = threadIdx.x;
    const int lane = tid & 31, wid = tid >> 5;
    const int wm = wid >> 1, wn = wid & 1;
    const int g = lane >> 2, tg = lane & 3;

    float acc[8][4];
#pragma unroll
    for (int j = 0; j < 8; j++)
#pragma unroll
        for (int i = 0; i < 4; i++) acc[j][i] = 0.f;

    for (int kc = 0; kc < K; kc += 32) {
        __syncthreads();
        {   // A tile 64x32 hi/lo: 1 uint4 (8 bf16) per thread per buffer
            int r = tid >> 2, c8 = (tid & 3) * 8;
            size_t go = (size_t)(m0 + r) * K + kc + c8;
            *(uint4*)&sA[0][r][c8] = *(const uint4*)(Ah + go);
            *(uint4*)&sA[1][r][c8] = *(const uint4*)(Al + go);
        }
#pragma unroll
        for (int i = 0; i < 2; i++) {  // B tile 128x32 hi/lo
            int idx = tid + i * 256;
            int r = idx >> 2, c8 = (idx & 3) * 8;
            size_t go = (size_t)(n0 + r) * K + kc + c8;
            *(uint4*)&sB[0][r][c8] = *(const uint4*)(Bh + go);
            *(uint4*)&sB[1][r][c8] = *(const uint4*)(Bl + go);
        }
        __syncthreads();

#pragma unroll
        for (int ks = 0; ks < 32; ks += 16) {
            const int ar = wm * 16 + g;
            uint32_t ah[4], al[4];
            ah[0] = *(const uint32_t*)&sA[0][ar][ks + 2 * tg];
            ah[1] = *(const uint32_t*)&sA[0][ar + 8][ks + 2 * tg];
            ah[2] = *(const uint32_t*)&sA[0][ar][ks + 2 * tg + 8];
            ah[3] = *(const uint32_t*)&sA[0][ar + 8][ks + 2 * tg + 8];
            al[0] = *(const uint32_t*)&sA[1][ar][ks + 2 * tg];
            al[1] = *(const uint32_t*)&sA[1][ar + 8][ks + 2 * tg];
            al[2] = *(const uint32_t*)&sA[1][ar][ks + 2 * tg + 8];
            al[3] = *(const uint32_t*)&sA[1][ar + 8][ks + 2 * tg + 8];
#pragma unroll
            for (int j = 0; j < 8; j++) {
                int bn = wn * 64 + j * 8 + g;
                uint32_t bh[2], bl[2];
                bh[0] = *(const uint32_t*)&sB[0][bn][ks + 2 * tg];
                bh[1] = *(const uint32_t*)&sB[0][bn][ks + 2 * tg + 8];
                bl[0] = *(const uint32_t*)&sB[1][bn][ks + 2 * tg];
                bl[1] = *(const uint32_t*)&sB[1][bn][ks + 2 * tg + 8];
                mma_bf16(acc[j], ah, bh);   // hi*hi
                mma_bf16(acc[j], ah, bl);   // hi*lo
                mma_bf16(acc[j], al, bh);   // lo*hi  (lo*lo dropped, ~2^-18)
            }
        }
    }

    // epilogue
    const int row0 = m0 + wm * 16 + g;
#pragma unroll
    for (int j = 0; j < 8; j++) {
        int col = n0 + wn * 64 + j * 8 + 2 * tg;
        float v0 = acc[j][0], v1 = acc[j][1], v2 = acc[j][2], v3 = acc[j][3];
        if (round_tf32) {
            v0 = __uint_as_float(f2tf32(v0));
            v1 = __uint_as_float(f2tf32(v1));
            v2 = __uint_as_float(f2tf32(v2));
            v3 = __uint_as_float(f2tf32(v3));
        }
        *(float2*)(C + (size_t)row0 * ldC + col)       = make_float2(v0, v1);
        *(float2*)(C + (size_t)(row0 + 8) * ldC + col) = make_float2(v2, v3);
    }
}

__global__ __launch_bounds__(256) void qkv_mma_kernel() {
    int z = blockIdx.y;
    float* Cz = (z == 0) ? g_Q : (z == 1) ? g_K : g_V;
    gemm_mma_body(g_xhi, g_xlo, g_wt_hi[z], g_wt_lo[z], Cz,
                  blockIdx.x * 64, 0, DMODEL, DK, true /*tf32-round for attention*/);
}

__global__ __launch_bounds__(256) void oproj_mma_kernel(float* __restrict__ out) {
    gemm_mma_body(g_Ohi, g_Olo, g_wot_hi, g_wot_lo, out,
                  blockIdx.x * 64, blockIdx.y * 128, DK, DMODEL, false);
}

// -------------------- flash attention, tf32 mma.sync --------------------
// CTA: 64 threads (2 warps), q-tile 32 (warp w owns queries w*16..w*16+15).
// Key chunks of 32. smem (floats, stride 132 -> conflict-free fragment lds):
#define QSTR 132
#define PSTR 36
#define AQ_OFF 0                       // Qs[32][132]
#define AK_OFF (32 * QSTR)             // Ks[32][132]
#define AV_OFF (2 * 32 * QSTR)         // Vs[32][132]
#define AP_OFF (3 * 32 * QSTR)         // Ps[32][36]
#define ATTN_SMEM_BYTES ((3 * 32 * QSTR + 32 * PSTR) * 4)

__global__ __launch_bounds__(64, 4) void attn_mma_kernel()
{
    extern __shared__ float sm[];
    float* Qs = sm + AQ_OFF;
    float* Ks = sm + AK_OFF;
    float* Vs = sm + AV_OFF;
    float* Ps = sm + AP_OFF;

    const int t = threadIdx.x;
    const int lane = t & 31, w = t >> 5;
    const int g = lane >> 2, tg = lane & 3;
    const int b = blockIdx.y;
    const int qt = (int)gridDim.x - 1 - (int)blockIdx.x;   // heavy tiles first
    const int q0 = qt * 32;
    const size_t bT = (size_t)b * TSEQ;

    // load Q tile [32][128] (already tf32-rounded by qkv epilogue)
#pragma unroll
    for (int i = 0; i < 16; i++) {
        int idx = t + i * 64;
        int r = idx >> 5, c4 = (idx & 31) * 4;
        *(float4*)&Qs[r * QSTR + c4] = *(const float4*)(g_Q + (bT + q0 + r) * DK + c4);
    }

    float oacc[16][4];
#pragma unroll
    for (int j = 0; j < 16; j++)
#pragma unroll
        for (int i = 0; i < 4; i++) oacc[j][i] = 0.f;
    float mr0 = -1e30f, mr1 = -1e30f, lr0 = 0.f, lr1 = 0.f;

    const int qrow0 = q0 + w * 16 + g;   // global query rows this thread owns
    const int qrow1 = qrow0 + 8;
    const int pr = w * 16 + g;           // local P row

    for (int kt = 0; kt <= qt; kt++) {
        const int k0 = kt * 32;
        __syncthreads();   // all warps done with previous K/V
#pragma unroll
        for (int i = 0; i < 16; i++) {
            int idx = t + i * 64;
            int r = idx >> 5, c4 = (idx & 31) * 4;
            *(float4*)&Ks[r * QSTR + c4] = *(const float4*)(g_K + (bT + k0 + r) * DK + c4);
            *(float4*)&Vs[r * QSTR + c4] = *(const float4*)(g_V + (bT + k0 + r) * DK + c4);
        }
        __syncthreads();

        // ---- S = Q @ K^T (m16 x n32 per warp, k=128) ----
        float sacc[4][4];
#pragma unroll
        for (int j = 0; j < 4; j++)
#pragma unroll
            for (int i = 0; i < 4; i++) sacc[j][i] = 0.f;

#pragma unroll
        for (int kk = 0; kk < 16; kk++) {
            uint32_t a[4];
            const int qr = w * 16 + g;
            a[0] = __float_as_uint(Qs[qr * QSTR + kk * 8 + tg]);
            a[1] = __float_as_uint(Qs[(qr + 8) * QSTR + kk * 8 + tg]);
            a[2] = __float_as_uint(Qs[qr * QSTR + kk * 8 + tg + 4]);
            a[3] = __float_as_uint(Qs[(qr + 8) * QSTR + kk * 8 + tg + 4]);
#pragma unroll
            for (int j = 0; j < 4; j++) {
                uint32_t bb[2];
                bb[0] = __float_as_uint(Ks[(j * 8 + g) * QSTR + kk * 8 + tg]);
                bb[1] = __float_as_uint(Ks[(j * 8 + g) * QSTR + kk * 8 + tg + 4]);
                mma_tf32(sacc[j], a, bb);
            }
        }

        // ---- mask (diag chunk only) + online softmax ----
        if (kt == qt) {
#pragma unroll
            for (int j = 0; j < 4; j++) {
                int c0 = k0 + j * 8 + 2 * tg, c1 = c0 + 1;
                if (c0 > qrow0) sacc[j][0] = -1e30f;
                if (c1 > qrow0) sacc[j][1] = -1e30f;
                if (c0 > qrow1) sacc[j][2] = -1e30f;
                if (c1 > qrow1) sacc[j][3] = -1e30f;
            }
        }
        float mx0 = -1e30f, mx1 = -1e30f;
#pragma unroll
        for (int j = 0; j < 4; j++) {
            mx0 = fmaxf(mx0, fmaxf(sacc[j][0], sacc[j][1]));
            mx1 = fmaxf(mx1, fmaxf(sacc[j][2], sacc[j][3]));
        }
        mx0 = fmaxf(mx0, __shfl_xor_sync(0xffffffffu, mx0, 1));
        mx0 = fmaxf(mx0, __shfl_xor_sync(0xffffffffu, mx0, 2));
        mx1 = fmaxf(mx1, __shfl_xor_sync(0xffffffffu, mx1, 1));
        mx1 = fmaxf(mx1, __shfl_xor_sync(0xffffffffu, mx1, 2));

        float mn0 = fmaxf(mr0, mx0), mn1 = fmaxf(mr1, mx1);
        float f0 = ex2f((mr0 - mn0) * C_LOG2);
        float f1 = ex2f((mr1 - mn1) * C_LOG2);
        mr0 = mn0; mr1 = mn1;

        float rs0 = 0.f, rs1 = 0.f;
#pragma unroll
        for (int j = 0; j < 4; j++) {
            float p00 = ex2f((sacc[j][0] - mn0) * C_LOG2);
            float p01 = ex2f((sacc[j][1] - mn0) * C_LOG2);
            float p10 = ex2f((sacc[j][2] - mn1) * C_LOG2);
            float p11 = ex2f((sacc[j][3] - mn1) * C_LOG2);
            rs0 += p00 + p01;
            rs1 += p10 + p11;
            *(float2*)&Ps[pr * PSTR + j * 8 + 2 * tg] =
                make_float2(__uint_as_float(f2tf32(p00)), __uint_as_float(f2tf32(p01)));
            *(float2*)&Ps[(pr + 8) * PSTR + j * 8 + 2 * tg] =
                make_float2(__uint_as_float(f2tf32(p10)), __uint_as_float(f2tf32(p11)));
        }
        rs0 += __shfl_xor_sync(0xffffffffu, rs0, 1);
        rs0 += __shfl_xor_sync(0xffffffffu, rs0, 2);
        rs1 += __shfl_xor_sync(0xffffffffu, rs1, 1);
        rs1 += __shfl_xor_sync(0xffffffffu, rs1, 2);
        lr0 = lr0 * f0 + rs0;
        lr1 = lr1 * f1 + rs1;

#pragma unroll
        for (int j = 0; j < 16; j++) {
            oacc[j][0] *= f0; oacc[j][1] *= f0;
            oacc[j][2] *= f1; oacc[j][3] *= f1;
        }
        __syncwarp();   // P visible warp-wide

        // ---- O += P @ V (m16 x n128 per warp, k=32) ----
#pragma unroll
        for (int kk = 0; kk < 4; kk++) {
            uint32_t a[4];
            a[0] = __float_as_uint(Ps[pr * PSTR + kk * 8 + tg]);
            a[1] = __float_as_uint(Ps[(pr + 8) * PSTR + kk * 8 + tg]);
            a[2] = __float_as_uint(Ps[pr * PSTR + kk * 8 + tg + 4]);
            a[3] = __float_as_uint(Ps[(pr + 8) * PSTR + kk * 8 + tg + 4]);
#pragma unroll
            for (int j = 0; j < 16; j++) {
                uint32_t bb[2];
                bb[0] = __float_as_uint(Vs[(kk * 8 + tg) * QSTR + j * 8 + g]);
                bb[1] = __float_as_uint(Vs[(kk * 8 + tg + 4) * QSTR + j * 8 + g]);
                mma_tf32(oacc[j], a, bb);
            }
        }
    }

    // ---- epilogue: normalize, write bf16 hi/lo for oproj ----
    float inv0 = 1.0f / lr0, inv1 = 1.0f / lr1;
    __nv_bfloat16* oh0 = g_Ohi + (bT + qrow0) * DK;
    __nv_bfloat16* ol0 = g_Olo + (bT + qrow0) * DK;
    __nv_bfloat16* oh1 = g_Ohi + (bT + qrow1) * DK;
    __nv_bfloat16* ol1 = g_Olo + (bT + qrow1) * DK;
#pragma unroll
    for (int j = 0; j < 16; j++) {
        int col = j * 8 + 2 * tg;
        uint32_t h, l;
        bf16split2(oacc[j][0] * inv0, oacc[j][1] * inv0, h, l);
        *(uint32_t*)(oh0 + col) = h;
        *(uint32_t*)(ol0 + col) = l;
        bf16split2(oacc[j][2] * inv1, oacc[j][3] * inv1, h, l);
        *(uint32_t*)(oh1 + col) = h;
        *(uint32_t*)(ol1 + col) = l;
    }
}

// -------------------- launch --------------------
extern "C" void kernel_launch(void* const* d_in, const int* in_sizes, int n_in,
                              void* d_out, int out_size)
{
    const float* x  = (const float*)d_in[0];
    const float* Wq = (const float*)d_in[1];
    const float* Wk = (const float*)d_in[2];
    const float* Wv = (const float*)d_in[3];
    const float* Wo = (const float*)d_in[4];
    float* out = (float*)d_out;

    static bool attr_set = false;
    if (!attr_set) {
        cudaFuncSetAttribute(attn_mma_kernel, cudaFuncAttributeMaxDynamicSharedMemorySize,
                             ATTN_SMEM_BYTES);
        attr_set = true;
    }

    // 0) precision-split conversions
    convert_x_kernel<<<(BATCH * TSEQ * DMODEL) / (256 * 4), 256>>>(x);
    convert_w_kernel<<<dim3((DMODEL * DK) / 256, 4), 256>>>(Wq, Wk, Wv, Wo);

    // 1) Q,K,V = x @ W  (bf16-split mma.sync; epilogue rounds to tf32)
    qkv_mma_kernel<<<dim3((BATCH * TSEQ) / 64, 3), 256>>>();

    // 2) causal flash attention (tf32 mma.sync)
    attn_mma_kernel<<<dim3(TSEQ / 32, BATCH), 64, ATTN_SMEM_BYTES>>>();

    // 3) out = O @ Wo  (bf16-split mma.sync)
    oproj_mma_kernel<<<dim3((BATCH * TSEQ) / 64, DMODEL / 128), 256>>>(out);
}